// round 2
// baseline (speedup 1.0000x reference)
#include <cuda_runtime.h>

// Problem dims
#define BB 64
#define TT 512
#define II 128
#define NN 2048
#define KTOT (NN + II)            // 2176 = recurrent 2048 + input 128
#define NTILES 16                 // n tiles of 128
#define KSPLIT 8                  // k slices
#define KSLICE (KTOT / KSPLIT)    // 272
#define KC 16                     // k chunk per smem stage
#define CHUNKS (KSLICE / KC)      // 17
#define GRID (NTILES * KSPLIT)    // 128 CTAs (all co-resident on 148 SMs)
#define NTHREADS 128

// Device-global scratch (no cudaMalloc allowed)
__device__ __align__(16) float g_WT[KTOT * NN];            // WT[k][n]: k<2048 -> W_eff[n][k], else W_inp[n][k-2048]
__device__ __align__(16) float g_h[2][BB * NN];            // ping-pong hidden state
__device__ __align__(16) float g_partial[KSPLIT][BB * NN]; // split-K partials
__device__ unsigned int g_arrive;                          // grid barrier counter (reset by memset each launch)

__device__ __forceinline__ unsigned long long fma2(unsigned long long a,
                                                   unsigned long long b,
                                                   unsigned long long c) {
    unsigned long long d;
    asm("fma.rn.f32x2 %0, %1, %2, %3;" : "=l"(d) : "l"(a), "l"(b), "l"(c));
    return d;
}

// ---------------- setup kernels ----------------

// Build WT[k][n] with a tiled transpose.
__global__ void build_wt(const float* __restrict__ Wrec, const float* __restrict__ Winp,
                         const int* __restrict__ mask, const int* __restrict__ sgn) {
    __shared__ float tile[32][33];
    int kb = blockIdx.x * 32;
    int nb = blockIdx.y * 32;
    int tx = threadIdx.x, ty = threadIdx.y;
#pragma unroll
    for (int r = 0; r < 32; r += 8) {
        int n = nb + ty + r;
        int k = kb + tx;
        float v;
        if (k < NN) {
            float w = Wrec[n * NN + k];
            int ms = mask[n * NN + k] * sgn[n * NN + k];
            v = fmaxf(w, 0.0f) * (float)ms;
        } else {
            v = Winp[n * II + (k - NN)];
        }
        tile[ty + r][tx] = v;
    }
    __syncthreads();
#pragma unroll
    for (int r = 0; r < 32; r += 8) {
        int k = kb + ty + r;
        int n = nb + tx;
        g_WT[k * NN + n] = tile[tx][ty + r];
    }
}

__global__ void init_h(const float* __restrict__ h0) {
    int i = blockIdx.x * blockDim.x + threadIdx.x;
    g_h[0][i] = h0[i];
}

// ---------------- persistent RNN kernel ----------------

__device__ __forceinline__ void grid_barrier(unsigned int target) {
    __threadfence();          // publish this thread's global stores
    __syncthreads();
    if (threadIdx.x == 0) {
        atomicAdd(&g_arrive, 1u);
        while (*(volatile unsigned int*)&g_arrive < target) {
            __nanosleep(64);
        }
        __threadfence();
    }
    __syncthreads();
}

__global__ void __launch_bounds__(NTHREADS, 1) rnn_persistent(
    const float* __restrict__ x,      // [B,T,I]
    const float* __restrict__ tonic,  // [N]
    float* __restrict__ out)          // [B,T,N]
{
    const int cta = blockIdx.x;
    const int nt  = cta & (NTILES - 1);
    const int ks  = cta >> 4;
    const int n0  = nt * 128;
    const int k0  = ks * KSLICE;
    const int tid = threadIdx.x;
    const int tx  = tid & 15;   // n-group (8 cols: tx*4..+3 and 64+tx*4..+3)
    const int ty  = tid >> 4;   // b-group (rows ty*8..ty*8+7)
    const int lm  = tid & 15;   // loader: k within chunk
    const int lb0 = tid >> 4;   // loader: b base

    __shared__ __align__(16) float As[KC][136];  // [m][2*b] duplicated pairs {v,v}
    __shared__ __align__(16) float Bs[KC][136];  // [m][n_local]

    const float A_ = 0.1f;
    const float OMA = 1.0f - A_;

    unsigned int bar = 0;

    for (int t = 0; t < TT; ++t) {
        const float* __restrict__ hc = g_h[t & 1];
        float* __restrict__ hn = g_h[(t + 1) & 1];

        unsigned long long acc[8][4];
#pragma unroll
        for (int i = 0; i < 8; ++i)
#pragma unroll
            for (int j = 0; j < 4; ++j) acc[i][j] = 0ull;

        float va[8], vb[16];

        // prefetch chunk 0 into registers
        {
            const int kc0 = k0;
            const int k = kc0 + lm;
#pragma unroll
            for (int j = 0; j < 8; ++j) {
                int b = lb0 + 8 * j;
                va[j] = (k < NN) ? fmaxf(__ldcg(&hc[b * NN + k]), 0.0f)
                                 : __ldg(&x[(b * TT + t) * II + (k - NN)]);
            }
#pragma unroll
            for (int j = 0; j < KC; ++j)
                vb[j] = g_WT[(kc0 + j) * NN + n0 + tid];
        }

        for (int c = 0; c < CHUNKS; ++c) {
            // stage registers -> smem
#pragma unroll
            for (int j = 0; j < 8; ++j) {
                int b = lb0 + 8 * j;
                *(float2*)&As[lm][2 * b] = make_float2(va[j], va[j]);
            }
#pragma unroll
            for (int j = 0; j < KC; ++j) Bs[j][tid] = vb[j];
            __syncthreads();

            // prefetch next chunk while computing this one
            if (c + 1 < CHUNKS) {
                const int kc0 = k0 + (c + 1) * KC;
                const int k = kc0 + lm;
#pragma unroll
                for (int j = 0; j < 8; ++j) {
                    int b = lb0 + 8 * j;
                    va[j] = (k < NN) ? fmaxf(__ldcg(&hc[b * NN + k]), 0.0f)
                                     : __ldg(&x[(b * TT + t) * II + (k - NN)]);
                }
#pragma unroll
                for (int j = 0; j < KC; ++j)
                    vb[j] = g_WT[(kc0 + j) * NN + n0 + tid];
            }

#pragma unroll
            for (int m = 0; m < KC; ++m) {
                ulonglong2 a01 = *(const ulonglong2*)&As[m][ty * 16 + 0];
                ulonglong2 a23 = *(const ulonglong2*)&As[m][ty * 16 + 4];
                ulonglong2 a45 = *(const ulonglong2*)&As[m][ty * 16 + 8];
                ulonglong2 a67 = *(const ulonglong2*)&As[m][ty * 16 + 12];
                ulonglong2 b01 = *(const ulonglong2*)&Bs[m][tx * 4];
                ulonglong2 b23 = *(const ulonglong2*)&Bs[m][64 + tx * 4];
                unsigned long long ap[8] = {a01.x, a01.y, a23.x, a23.y,
                                            a45.x, a45.y, a67.x, a67.y};
                unsigned long long bp[4] = {b01.x, b01.y, b23.x, b23.y};
#pragma unroll
                for (int i = 0; i < 8; ++i)
#pragma unroll
                    for (int j = 0; j < 4; ++j)
                        acc[i][j] = fma2(ap[i], bp[j], acc[i][j]);
            }
            __syncthreads();
        }

        // store split-K partials
#pragma unroll
        for (int i = 0; i < 8; ++i) {
            int b = ty * 8 + i;
            union { unsigned long long u[2]; float4 f; } u0, u1;
            u0.u[0] = acc[i][0]; u0.u[1] = acc[i][1];
            u1.u[0] = acc[i][2]; u1.u[1] = acc[i][3];
            float* dst = &g_partial[ks][b * NN + n0];
            *(float4*)&dst[tx * 4]      = u0.f;
            *(float4*)&dst[64 + tx * 4] = u1.f;
        }

        bar += GRID;
        grid_barrier(bar);

        // reduce partials + leaky update + relu + output write
        {
            int gid = cta * NTHREADS + tid;      // 0..16383
            int off = gid * 8;                   // flat [b][n] offset, 8 floats
            int b = off >> 11;                   // /N
            int n = off & (NN - 1);

            float4 s0 = make_float4(0.f, 0.f, 0.f, 0.f);
            float4 s1 = make_float4(0.f, 0.f, 0.f, 0.f);
#pragma unroll
            for (int p = 0; p < KSPLIT; ++p) {
                float4 q0 = __ldcg((const float4*)&g_partial[p][off]);
                float4 q1 = __ldcg((const float4*)&g_partial[p][off + 4]);
                s0.x += q0.x; s0.y += q0.y; s0.z += q0.z; s0.w += q0.w;
                s1.x += q1.x; s1.y += q1.y; s1.z += q1.z; s1.w += q1.w;
            }
            float4 tn0 = *(const float4*)&tonic[n];
            float4 tn1 = *(const float4*)&tonic[n + 4];
            float4 h0v = __ldcg((const float4*)&hc[off]);
            float4 h1v = __ldcg((const float4*)&hc[off + 4]);

            float4 r0, r1;
            r0.x = OMA * h0v.x + A_ * (s0.x + tn0.x);
            r0.y = OMA * h0v.y + A_ * (s0.y + tn0.y);
            r0.z = OMA * h0v.z + A_ * (s0.z + tn0.z);
            r0.w = OMA * h0v.w + A_ * (s0.w + tn0.w);
            r1.x = OMA * h1v.x + A_ * (s1.x + tn1.x);
            r1.y = OMA * h1v.y + A_ * (s1.y + tn1.y);
            r1.z = OMA * h1v.z + A_ * (s1.z + tn1.z);
            r1.w = OMA * h1v.w + A_ * (s1.w + tn1.w);

            *(float4*)&hn[off]     = r0;
            *(float4*)&hn[off + 4] = r1;

            float4 o0, o1;
            o0.x = fmaxf(r0.x, 0.f); o0.y = fmaxf(r0.y, 0.f);
            o0.z = fmaxf(r0.z, 0.f); o0.w = fmaxf(r0.w, 0.f);
            o1.x = fmaxf(r1.x, 0.f); o1.y = fmaxf(r1.y, 0.f);
            o1.z = fmaxf(r1.z, 0.f); o1.w = fmaxf(r1.w, 0.f);
            float* op = &out[(size_t)(b * TT + t) * NN + n];
            *(float4*)&op[0] = o0;
            *(float4*)&op[4] = o1;
        }

        bar += GRID;
        grid_barrier(bar);
    }
}

// ---------------- launch ----------------

extern "C" void kernel_launch(void* const* d_in, const int* in_sizes, int n_in,
                              void* d_out, int out_size) {
    const float* x     = (const float*)d_in[0];
    const float* h0    = (const float*)d_in[1];
    const float* Wrec  = (const float*)d_in[2];
    const float* Winp  = (const float*)d_in[3];
    const float* tonic = (const float*)d_in[4];
    const int*   mask  = (const int*)d_in[5];
    const int*   sgn   = (const int*)d_in[6];
    float* out = (float*)d_out;

    // reset grid-barrier counter (graph-capturable, deterministic per launch)
    void* pa = nullptr;
    cudaGetSymbolAddress(&pa, g_arrive);
    cudaMemsetAsync(pa, 0, sizeof(unsigned int));

    build_wt<<<dim3(KTOT / 32, NN / 32), dim3(32, 8)>>>(Wrec, Winp, mask, sgn);
    init_h<<<(BB * NN) / 256, 256>>>(h0);
    rnn_persistent<<<GRID, NTHREADS>>>(x, tonic, out);
}

// round 4
// speedup vs baseline: 1.8966x; 1.8966x over previous
#include <cuda_runtime.h>
#include <cuda_bf16.h>
#include <cstdint>

// ---------------- problem dims ----------------
#define BB 64
#define TT 512
#define II 128
#define NN 2048
#define NTILES 16            // n tiles of 128
#define KSP 9                // 8 recurrent k-slices of 256 + 1 input slice
#define KSLICE 256
#define GRID (NTILES * KSP)  // 144 CTAs, co-resident on 148 SMs
#define NTHREADS 128

// ---------------- smem layout (bytes from 1024-aligned base) ----------------
#define A_STRIDE 528                     // 256 bf16 + 16B pad (conflict-free ldmatrix)
#define B_STRIDE 144                     // 64 bf16 + 16B pad
#define A_HI 0
#define A_LO (128 * A_STRIDE)            // 67584
#define B_HI (2 * 128 * A_STRIDE)        // 135168
#define B_LO (B_HI + 256 * B_STRIDE)     // 172032
#define SMEM_DYN (B_LO + 256 * B_STRIDE + 1024)  // 209920

// ---------------- device globals (no cudaMalloc allowed) ----------------
__device__ float g_h[2][NN * BB];                 // hidden state, [n][b]
__device__ float g_partial[KSP][NN * BB];         // split-K partials, [n][b]
__device__ __nv_bfloat16 g_rhi[NN * BB];          // relu(h) hi, [n][b]
__device__ __nv_bfloat16 g_rlo[NN * BB];          // relu(h) lo
__device__ __nv_bfloat16 g_xhi[TT * II * BB];     // x hi, [t][i][b]
__device__ __nv_bfloat16 g_xlo[TT * II * BB];
__device__ unsigned int g_arrive;

// ---------------- helpers ----------------
__device__ __forceinline__ uint32_t smem_u32(const void* p) {
    uint32_t a;
    asm("{ .reg .u64 t; cvta.to.shared.u64 t, %1; cvt.u32.u64 %0, t; }" : "=r"(a) : "l"(p));
    return a;
}

__device__ __forceinline__ void ldsm4(uint32_t* r, uint32_t addr) {
    asm volatile("ldmatrix.sync.aligned.m8n8.x4.shared.b16 {%0,%1,%2,%3}, [%4];"
                 : "=r"(r[0]), "=r"(r[1]), "=r"(r[2]), "=r"(r[3]) : "r"(addr));
}
__device__ __forceinline__ void ldsm4t(uint32_t* r, uint32_t addr) {
    asm volatile("ldmatrix.sync.aligned.m8n8.x4.trans.shared.b16 {%0,%1,%2,%3}, [%4];"
                 : "=r"(r[0]), "=r"(r[1]), "=r"(r[2]), "=r"(r[3]) : "r"(addr));
}
__device__ __forceinline__ void mma16816(float* d, const uint32_t* a, const uint32_t* b) {
    asm volatile(
        "mma.sync.aligned.m16n8k16.row.col.f32.bf16.bf16.f32 "
        "{%0,%1,%2,%3}, {%4,%5,%6,%7}, {%8,%9}, {%0,%1,%2,%3};"
        : "+f"(d[0]), "+f"(d[1]), "+f"(d[2]), "+f"(d[3])
        : "r"(a[0]), "r"(a[1]), "r"(a[2]), "r"(a[3]), "r"(b[0]), "r"(b[1]));
}

__device__ __forceinline__ void grid_barrier(unsigned int target) {
    __threadfence();
    __syncthreads();
    if (threadIdx.x == 0) {
        atomicAdd(&g_arrive, 1u);
        while (*(volatile unsigned int*)&g_arrive < target) { __nanosleep(32); }
        __threadfence();
    }
    __syncthreads();
}

// ---------------- setup kernels ----------------
__global__ void init_h(const float* __restrict__ h0) {
    int i = blockIdx.x * blockDim.x + threadIdx.x;   // i = n*64 + b
    int n = i >> 6, b = i & 63;
    float h = h0[b * NN + n];
    g_h[0][i] = h;
    float r = fmaxf(h, 0.0f);
    __nv_bfloat16 hi = __float2bfloat16(r);
    g_rhi[i] = hi;
    g_rlo[i] = __float2bfloat16(r - __bfloat162float(hi));
}

__global__ void prep_x(const float* __restrict__ x) {
    int gid = blockIdx.x * blockDim.x + threadIdx.x; // gid = (t*II + i)*64 + b
    int b = gid & 63;
    int i = (gid >> 6) & (II - 1);
    int t = gid >> 13;
    float v = x[((size_t)b * TT + t) * II + i];
    __nv_bfloat16 hi = __float2bfloat16(v);
    g_xhi[gid] = hi;
    g_xlo[gid] = __float2bfloat16(v - __bfloat162float(hi));
}

// ---------------- persistent RNN kernel ----------------
__global__ void __launch_bounds__(NTHREADS, 1) rnn_persistent(
    const float* __restrict__ Wrec,   // [N,N]
    const float* __restrict__ Winp,   // [N,I]
    const float* __restrict__ tonic,  // [N]
    const int*   __restrict__ mask,   // [N,N]
    const int*   __restrict__ sgn,    // [N,N]
    float* __restrict__ out)          // [B,T,N]
{
    extern __shared__ char dyn_raw[];
    char* sm = (char*)(((uintptr_t)dyn_raw + 1023) & ~(uintptr_t)1023);
    const uint32_t smb = smem_u32(sm);

    const int cta = blockIdx.x;
    const int nt  = cta % NTILES;           // 0..15
    const int ks  = cta / NTILES;           // 0..8
    const int n0  = nt * 128;
    const int k0  = ks * KSLICE;
    const int tid = threadIdx.x;
    const int wid = tid >> 5;
    const int lane = tid & 31;
    const int m0  = wid * 32;               // warp's 32 D-rows within tile
    const bool inp = (ks == KSP - 1);
    const int KSTEPS = inp ? (II / 16) : (KSLICE / 16);   // 8 or 16

    // ---- build A (W slice) in SMEM as bf16 hi/lo, once ----
    for (int idx = tid; idx < 128 * 256; idx += NTHREADS) {
        int m = idx >> 8, c = idx & 255;
        int n = n0 + m;
        float v = 0.0f;
        if (!inp) {
            int k = k0 + c;
            float w = Wrec[n * NN + k];
            int ms = mask[n * NN + k] * sgn[n * NN + k];
            v = fmaxf(w, 0.0f) * (float)ms;
        } else if (c < II) {
            v = Winp[n * II + c];
        }
        __nv_bfloat16 hi = __float2bfloat16(v);
        __nv_bfloat16 lo = __float2bfloat16(v - __bfloat162float(hi));
        *(__nv_bfloat16*)(sm + A_HI + m * A_STRIDE + c * 2) = hi;
        *(__nv_bfloat16*)(sm + A_LO + m * A_STRIDE + c * 2) = lo;
    }
    __syncthreads();

    // per-thread ldmatrix base addresses
    const uint32_t aBase = smb + A_HI + (uint32_t)(m0 + (lane & 15)) * A_STRIDE
                           + (uint32_t)(lane >> 4) * 16;
    const uint32_t bBase = smb + B_HI
                           + (uint32_t)((lane & 7) + ((lane >> 3) & 1) * 8) * B_STRIDE
                           + (uint32_t)(lane >> 4) * 16;

    const float AC = 0.1f, OMA = 0.9f;
    unsigned int bar = 0;

    for (int t = 0; t < TT; ++t) {
        const float* __restrict__ cur = g_h[t & 1];
        float* __restrict__ nxt = g_h[(t + 1) & 1];

        // ---- phase 1: copy B tile (bf16 hi/lo, already split by producer) ----
        {
            const char* srcHi = inp ? (const char*)&g_xhi[(size_t)t * II * BB]
                                    : (const char*)&g_rhi[(size_t)k0 * BB];
            const char* srcLo = inp ? (const char*)&g_xlo[(size_t)t * II * BB]
                                    : (const char*)&g_rlo[(size_t)k0 * BB];
            const int rows = inp ? II : KSLICE;
            for (int idx = tid; idx < rows * 8; idx += NTHREADS) {
                int r = idx >> 3, c16 = (idx & 7) * 16;
                uint4 vh = __ldcg((const uint4*)(srcHi + r * 128 + c16));
                uint4 vl = __ldcg((const uint4*)(srcLo + r * 128 + c16));
                *(uint4*)(sm + B_HI + r * B_STRIDE + c16) = vh;
                *(uint4*)(sm + B_LO + r * B_STRIDE + c16) = vl;
            }
        }
        __syncthreads();

        // ---- phase 2: 3-term double-bf16 MMA ----
        float acc[2][8][4];
#pragma unroll
        for (int i = 0; i < 2; ++i)
#pragma unroll
            for (int j = 0; j < 8; ++j)
#pragma unroll
                for (int q = 0; q < 4; ++q) acc[i][j][q] = 0.0f;

#pragma unroll 1
        for (int kk = 0; kk < KSTEPS; ++kk) {
            uint32_t ahi[2][4], alo[2][4];
            const uint32_t aA = aBase + (uint32_t)kk * 32;
            ldsm4(ahi[0], aA);
            ldsm4(ahi[1], aA + 16 * A_STRIDE);
            ldsm4(alo[0], aA + (A_LO - A_HI));
            ldsm4(alo[1], aA + (A_LO - A_HI) + 16 * A_STRIDE);

            uint32_t bhi[8][2], blo[8][2];
            const uint32_t bA = bBase + (uint32_t)kk * 16 * B_STRIDE;
#pragma unroll
            for (int p = 0; p < 4; ++p) {
                ldsm4t(&bhi[2 * p][0], bA + p * 32);
                ldsm4t(&blo[2 * p][0], bA + p * 32 + (B_LO - B_HI));
            }

#pragma unroll
            for (int mt = 0; mt < 2; ++mt)
#pragma unroll
                for (int nb = 0; nb < 8; ++nb) {
                    mma16816(acc[mt][nb], ahi[mt], bhi[nb]);
                    mma16816(acc[mt][nb], ahi[mt], blo[nb]);
                    mma16816(acc[mt][nb], alo[mt], bhi[nb]);
                }
        }

        // ---- phase 3: store split-K partial ----
        {
            float* dst = &g_partial[ks][0];
            const int gi = lane >> 2;       // 0..7
            const int ti = lane & 3;
#pragma unroll
            for (int mt = 0; mt < 2; ++mt) {
                int r0 = n0 + m0 + mt * 16 + gi;
#pragma unroll
                for (int nb = 0; nb < 8; ++nb) {
                    int cb = nb * 8 + 2 * ti;
                    __stcg((float2*)&dst[r0 * BB + cb],
                           make_float2(acc[mt][nb][0], acc[mt][nb][1]));
                    __stcg((float2*)&dst[(r0 + 8) * BB + cb],
                           make_float2(acc[mt][nb][2], acc[mt][nb][3]));
                }
            }
        }

        bar += GRID;
        grid_barrier(bar);

        // ---- phase 4: reduce partials + leaky update + relu + outputs ----
        {
            int gid = cta * NTHREADS + tid;
            if (gid < (NN * BB) / 8) {
                int base = gid * 8;           // flat [n][b], 8 consecutive b
                int n = base >> 6;
                int b0 = base & 63;
                float4 s0 = make_float4(0.f, 0.f, 0.f, 0.f);
                float4 s1 = make_float4(0.f, 0.f, 0.f, 0.f);
#pragma unroll
                for (int p = 0; p < KSP; ++p) {
                    float4 q0 = __ldcg((const float4*)&g_partial[p][base]);
                    float4 q1 = __ldcg((const float4*)&g_partial[p][base + 4]);
                    s0.x += q0.x; s0.y += q0.y; s0.z += q0.z; s0.w += q0.w;
                    s1.x += q1.x; s1.y += q1.y; s1.z += q1.z; s1.w += q1.w;
                }
                float tn = __ldg(&tonic[n]);
                float4 h0v = __ldcg((const float4*)&cur[base]);
                float4 h1v = __ldcg((const float4*)&cur[base + 4]);
                float4 r0, r1;
                r0.x = OMA * h0v.x + AC * (s0.x + tn);
                r0.y = OMA * h0v.y + AC * (s0.y + tn);
                r0.z = OMA * h0v.z + AC * (s0.z + tn);
                r0.w = OMA * h0v.w + AC * (s0.w + tn);
                r1.x = OMA * h1v.x + AC * (s1.x + tn);
                r1.y = OMA * h1v.y + AC * (s1.y + tn);
                r1.z = OMA * h1v.z + AC * (s1.z + tn);
                r1.w = OMA * h1v.w + AC * (s1.w + tn);
                __stcg((float4*)&nxt[base], r0);
                __stcg((float4*)&nxt[base + 4], r1);

                float rr[8] = {fmaxf(r0.x, 0.f), fmaxf(r0.y, 0.f),
                               fmaxf(r0.z, 0.f), fmaxf(r0.w, 0.f),
                               fmaxf(r1.x, 0.f), fmaxf(r1.y, 0.f),
                               fmaxf(r1.z, 0.f), fmaxf(r1.w, 0.f)};

                // producer-side bf16 hi/lo split of r for next step's B tiles
                __nv_bfloat16 hi8[8], lo8[8];
#pragma unroll
                for (int i = 0; i < 8; ++i) {
                    hi8[i] = __float2bfloat16(rr[i]);
                    lo8[i] = __float2bfloat16(rr[i] - __bfloat162float(hi8[i]));
                }
                *(uint4*)&g_rhi[base] = *(uint4*)hi8;
                *(uint4*)&g_rlo[base] = *(uint4*)lo8;

                // output rates
#pragma unroll
                for (int i = 0; i < 8; ++i)
                    out[((size_t)(b0 + i) * TT + t) * NN + n] = rr[i];
            }
        }

        bar += GRID;
        grid_barrier(bar);
    }
}

// ---------------- launch ----------------
extern "C" void kernel_launch(void* const* d_in, const int* in_sizes, int n_in,
                              void* d_out, int out_size) {
    const float* x     = (const float*)d_in[0];
    const float* h0    = (const float*)d_in[1];
    const float* Wrec  = (const float*)d_in[2];
    const float* Winp  = (const float*)d_in[3];
    const float* tonic = (const float*)d_in[4];
    const int*   mask  = (const int*)d_in[5];
    const int*   sgn   = (const int*)d_in[6];
    float* out = (float*)d_out;

    cudaFuncSetAttribute(rnn_persistent,
                         cudaFuncAttributeMaxDynamicSharedMemorySize, SMEM_DYN);

    void* pa = nullptr;
    cudaGetSymbolAddress(&pa, g_arrive);
    cudaMemsetAsync(pa, 0, sizeof(unsigned int));

    init_h<<<(NN * BB) / 256, 256>>>(h0);
    prep_x<<<(TT * II * BB) / 256, 256>>>(x);
    rnn_persistent<<<GRID, NTHREADS, SMEM_DYN>>>(Wrec, Winp, tonic, mask, sgn, out);
}

// round 5
// speedup vs baseline: 2.5207x; 1.3291x over previous
#include <cuda_runtime.h>
#include <cuda_bf16.h>
#include <cstdint>

// ---------------- problem dims ----------------
#define BB 64
#define TT 512
#define II 128
#define NN 2048
#define NTILES 16            // n tiles of 128
#define KSP 9                // 8 recurrent k-slices of 256 + 1 input slice
#define KSLICE 256
#define GRID (NTILES * KSP)  // 144 CTAs, co-resident (1 per SM)
#define NTHREADS 256         // 8 warps

// ---------------- smem layout (bytes) ----------------
#define A_STRIDE 528                     // 256 bf16 + 16B pad
#define B_STRIDE 144                     // 64 bf16 + 16B pad
#define A_HI 0
#define A_LO (128 * A_STRIDE)            // 67584
#define B_HI (2 * 128 * A_STRIDE)        // 135168
#define B_LO (B_HI + 256 * B_STRIDE)     // 172032
#define SMEM_DYN (B_LO + 256 * B_STRIDE) // 208896

// ---------------- device globals ----------------
__device__ float g_h[2][NN * BB];                 // hidden state, [n][b]
__device__ float g_partial[KSP][NN * BB];         // split-K partials, [n][b]
__device__ __nv_bfloat16 g_rhi[NN * BB];          // relu(h) hi, [n][b]
__device__ __nv_bfloat16 g_rlo[NN * BB];          // relu(h) lo
__device__ __nv_bfloat16 g_xhi[TT * II * BB];     // x hi, [t][i][b]
__device__ __nv_bfloat16 g_xlo[TT * II * BB];
__device__ unsigned int g_arrive;

// ---------------- helpers ----------------
__device__ __forceinline__ uint32_t smem_u32(const void* p) {
    uint32_t a;
    asm("{ .reg .u64 t; cvta.to.shared.u64 t, %1; cvt.u32.u64 %0, t; }" : "=r"(a) : "l"(p));
    return a;
}
__device__ __forceinline__ void ldsm4(uint32_t* r, uint32_t addr) {
    asm volatile("ldmatrix.sync.aligned.m8n8.x4.shared.b16 {%0,%1,%2,%3}, [%4];"
                 : "=r"(r[0]), "=r"(r[1]), "=r"(r[2]), "=r"(r[3]) : "r"(addr));
}
__device__ __forceinline__ void ldsm4t(uint32_t* r, uint32_t addr) {
    asm volatile("ldmatrix.sync.aligned.m8n8.x4.trans.shared.b16 {%0,%1,%2,%3}, [%4];"
                 : "=r"(r[0]), "=r"(r[1]), "=r"(r[2]), "=r"(r[3]) : "r"(addr));
}
__device__ __forceinline__ void mma16816(float* d, const uint32_t* a, const uint32_t* b) {
    asm volatile(
        "mma.sync.aligned.m16n8k16.row.col.f32.bf16.bf16.f32 "
        "{%0,%1,%2,%3}, {%4,%5,%6,%7}, {%8,%9}, {%0,%1,%2,%3};"
        : "+f"(d[0]), "+f"(d[1]), "+f"(d[2]), "+f"(d[3])
        : "r"(a[0]), "r"(a[1]), "r"(a[2]), "r"(a[3]), "r"(b[0]), "r"(b[1]));
}
__device__ __forceinline__ void grid_barrier(unsigned int target) {
    __threadfence();
    __syncthreads();
    if (threadIdx.x == 0) {
        atomicAdd(&g_arrive, 1u);
        while (*(volatile unsigned int*)&g_arrive < target) { __nanosleep(32); }
        __threadfence();
    }
    __syncthreads();
}

__device__ __forceinline__ void load_frags(uint32_t aBase, uint32_t bBase, int kk,
                                           uint32_t* ahi, uint32_t* alo,
                                           uint32_t (*bhi)[2], uint32_t (*blo)[2]) {
    const uint32_t aA = aBase + (uint32_t)kk * 32;
    ldsm4(ahi, aA);
    ldsm4(alo, aA + (A_LO - A_HI));
    const uint32_t bA = bBase + (uint32_t)kk * 16 * B_STRIDE;
#pragma unroll
    for (int p = 0; p < 4; ++p) {
        ldsm4t(&bhi[2 * p][0], bA + p * 32);
        ldsm4t(&blo[2 * p][0], bA + p * 32 + (B_LO - B_HI));
    }
}

// ---------------- persistent RNN kernel (includes all setup) ----------------
__global__ void __launch_bounds__(NTHREADS, 1) rnn_persistent(
    const float* __restrict__ x,      // [B,T,I]
    const float* __restrict__ h0,     // [B,N]
    const float* __restrict__ Wrec,   // [N,N]
    const float* __restrict__ Winp,   // [N,I]
    const float* __restrict__ tonic,  // [N]
    const int*   __restrict__ mask,   // [N,N]
    const int*   __restrict__ sgn,    // [N,N]
    float* __restrict__ out)          // [B,T,N]
{
    extern __shared__ __align__(16) char sm[];
    const uint32_t smb = smem_u32(sm);
    __shared__ float sm_out[64][17];  // out staging [b][r], padded

    const int cta = blockIdx.x;
    const int nt  = cta % NTILES;
    const int ks  = cta / NTILES;
    const int n0  = nt * 128;
    const int k0  = ks * KSLICE;
    const int tid = threadIdx.x;
    const int wid = tid >> 5;
    const int lane = tid & 31;
    const bool inp = (ks == KSP - 1);
    const int KSTEPS = inp ? (II / 16) : (KSLICE / 16);

    // ======== prologue (once) ========
    // A (W slice) -> smem bf16 hi/lo
    for (int idx = tid; idx < 128 * 256; idx += NTHREADS) {
        int m = idx >> 8, c = idx & 255;
        int n = n0 + m;
        float v = 0.0f;
        if (!inp) {
            int k = k0 + c;
            float w = Wrec[n * NN + k];
            int ms = mask[n * NN + k] * sgn[n * NN + k];
            v = fmaxf(w, 0.0f) * (float)ms;
        } else if (c < II) {
            v = Winp[n * II + c];
        }
        __nv_bfloat16 hi = __float2bfloat16(v);
        __nv_bfloat16 lo = __float2bfloat16(v - __bfloat162float(hi));
        *(__nv_bfloat16*)(sm + A_HI + m * A_STRIDE + c * 2) = hi;
        *(__nv_bfloat16*)(sm + A_LO + m * A_STRIDE + c * 2) = lo;
    }
    // h0 -> g_h[0], g_rhi/g_rlo  ([n][b] layout)
    {
        int gid = cta * NTHREADS + tid;
        if (gid < (NN * BB) / 4) {
            int base = gid * 4;               // n = base>>6, b0 = base&63
            int n = base >> 6, b0 = base & 63;
            float hv[4];
#pragma unroll
            for (int u = 0; u < 4; ++u) hv[u] = h0[(size_t)(b0 + u) * NN + n];
            *(float4*)&g_h[0][base] = make_float4(hv[0], hv[1], hv[2], hv[3]);
            __nv_bfloat16 hi4[4], lo4[4];
#pragma unroll
            for (int u = 0; u < 4; ++u) {
                float r = fmaxf(hv[u], 0.0f);
                hi4[u] = __float2bfloat16(r);
                lo4[u] = __float2bfloat16(r - __bfloat162float(hi4[u]));
            }
            *(uint2*)&g_rhi[base] = *(uint2*)hi4;
            *(uint2*)&g_rlo[base] = *(uint2*)lo4;
        }
    }
    // x -> g_xhi/g_xlo  ([t][i][b] layout)
    for (int gid = cta * NTHREADS + tid; gid < (TT * II * BB) / 4; gid += GRID * NTHREADS) {
        int base = gid * 4;                   // flat (t*II+i)*64 + b
        int b0 = base & 63;
        int i  = (base >> 6) & (II - 1);
        int t  = base >> 13;
        __nv_bfloat16 hi4[4], lo4[4];
#pragma unroll
        for (int u = 0; u < 4; ++u) {
            float v = __ldg(&x[((size_t)(b0 + u) * TT + t) * II + i]);
            hi4[u] = __float2bfloat16(v);
            lo4[u] = __float2bfloat16(v - __bfloat162float(hi4[u]));
        }
        *(uint2*)&g_xhi[base] = *(uint2*)hi4;
        *(uint2*)&g_xlo[base] = *(uint2*)lo4;
    }

    unsigned int bar = GRID;
    grid_barrier(bar);

    // per-thread ldmatrix base addresses (m16 tile per warp)
    const uint32_t aBase = smb + A_HI + (uint32_t)(wid * 16 + (lane & 15)) * A_STRIDE
                           + (uint32_t)(lane >> 4) * 16;
    const uint32_t bBase = smb + B_HI
                           + (uint32_t)((lane & 7) + ((lane >> 3) & 1) * 8) * B_STRIDE
                           + (uint32_t)(lane >> 4) * 16;

    // reduce-phase ownership: contiguous n rows
    const int Rrows = (cta < 32) ? 15 : 14;
    const int nbase = cta * 14 + min(cta, 32);

    const float AC = 0.1f, OMA = 0.9f;

    for (int t = 0; t < TT; ++t) {
        const float* __restrict__ cur = g_h[t & 1];
        float* __restrict__ nxt = g_h[(t + 1) & 1];

        // ---- phase 1: copy B tile ----
        {
            const char* srcHi = inp ? (const char*)&g_xhi[(size_t)t * II * BB]
                                    : (const char*)&g_rhi[(size_t)k0 * BB];
            const char* srcLo = inp ? (const char*)&g_xlo[(size_t)t * II * BB]
                                    : (const char*)&g_rlo[(size_t)k0 * BB];
            const int rows = inp ? II : KSLICE;
            for (int idx = tid; idx < rows * 8; idx += NTHREADS) {
                int r = idx >> 3, c16 = (idx & 7) * 16;
                uint4 vh = __ldcg((const uint4*)(srcHi + r * 128 + c16));
                uint4 vl = __ldcg((const uint4*)(srcLo + r * 128 + c16));
                *(uint4*)(sm + B_HI + r * B_STRIDE + c16) = vh;
                *(uint4*)(sm + B_LO + r * B_STRIDE + c16) = vl;
            }
        }
        __syncthreads();

        // ---- phase 2: pipelined 3-term double-bf16 MMA ----
        float acc[8][4];
#pragma unroll
        for (int j = 0; j < 8; ++j)
#pragma unroll
            for (int q = 0; q < 4; ++q) acc[j][q] = 0.0f;

        uint32_t ahi[2][4], alo[2][4], bhi[2][8][2], blo[2][8][2];
        load_frags(aBase, bBase, 0, ahi[0], alo[0], bhi[0], blo[0]);

#pragma unroll 2
        for (int kk = 0; kk < KSTEPS; ++kk) {
            const int cb = kk & 1;
            if (kk + 1 < KSTEPS)
                load_frags(aBase, bBase, kk + 1, ahi[cb ^ 1], alo[cb ^ 1],
                           bhi[cb ^ 1], blo[cb ^ 1]);
#pragma unroll
            for (int nb = 0; nb < 8; ++nb) {
                mma16816(acc[nb], ahi[cb], bhi[cb][nb]);
                mma16816(acc[nb], ahi[cb], blo[cb][nb]);
                mma16816(acc[nb], alo[cb], bhi[cb][nb]);
            }
        }

        // ---- phase 3: store split-K partial ----
        {
            float* dst = &g_partial[ks][0];
            const int gi = lane >> 2;
            const int ti = lane & 3;
            const int r0 = n0 + wid * 16 + gi;
#pragma unroll
            for (int nb = 0; nb < 8; ++nb) {
                int cb2 = nb * 8 + 2 * ti;
                __stcg((float2*)&dst[(size_t)r0 * BB + cb2],
                       make_float2(acc[nb][0], acc[nb][1]));
                __stcg((float2*)&dst[(size_t)(r0 + 8) * BB + cb2],
                       make_float2(acc[nb][2], acc[nb][3]));
            }
        }

        bar += GRID;
        grid_barrier(bar);

        // ---- phase 4: reduce + update + relu + staged coalesced out ----
        if (tid < Rrows * 16) {
            int r = tid >> 4;
            int b0 = (tid & 15) * 4;
            int n = nbase + r;
            size_t off = (size_t)n * BB + b0;

            float4 s = make_float4(0.f, 0.f, 0.f, 0.f);
#pragma unroll
            for (int p = 0; p < KSP; ++p) {
                float4 q = __ldcg((const float4*)&g_partial[p][off]);
                s.x += q.x; s.y += q.y; s.z += q.z; s.w += q.w;
            }
            float tn = __ldg(&tonic[n]);
            float4 hv = __ldcg((const float4*)&cur[off]);
            float4 r4;
            r4.x = OMA * hv.x + AC * (s.x + tn);
            r4.y = OMA * hv.y + AC * (s.y + tn);
            r4.z = OMA * hv.z + AC * (s.z + tn);
            r4.w = OMA * hv.w + AC * (s.w + tn);
            __stcg((float4*)&nxt[off], r4);

            float rr[4] = {fmaxf(r4.x, 0.f), fmaxf(r4.y, 0.f),
                           fmaxf(r4.z, 0.f), fmaxf(r4.w, 0.f)};
            __nv_bfloat16 hi4[4], lo4[4];
#pragma unroll
            for (int u = 0; u < 4; ++u) {
                hi4[u] = __float2bfloat16(rr[u]);
                lo4[u] = __float2bfloat16(rr[u] - __bfloat162float(hi4[u]));
                sm_out[b0 + u][r] = rr[u];
            }
            *(uint2*)&g_rhi[off] = *(uint2*)hi4;
            *(uint2*)&g_rlo[off] = *(uint2*)lo4;
        }
        __syncthreads();

        // coalesced out: runs of Rrows contiguous floats per b
        for (int idx = tid; idx < Rrows * 64; idx += NTHREADS) {
            int b = idx / Rrows;
            int rr2 = idx - b * Rrows;
            out[((size_t)b * TT + t) * NN + nbase + rr2] = sm_out[b][rr2];
        }

        bar += GRID;
        grid_barrier(bar);
    }
}

// ---------------- launch ----------------
extern "C" void kernel_launch(void* const* d_in, const int* in_sizes, int n_in,
                              void* d_out, int out_size) {
    const float* x     = (const float*)d_in[0];
    const float* h0    = (const float*)d_in[1];
    const float* Wrec  = (const float*)d_in[2];
    const float* Winp  = (const float*)d_in[3];
    const float* tonic = (const float*)d_in[4];
    const int*   mask  = (const int*)d_in[5];
    const int*   sgn   = (const int*)d_in[6];
    float* out = (float*)d_out;

    cudaFuncSetAttribute(rnn_persistent,
                         cudaFuncAttributeMaxDynamicSharedMemorySize, SMEM_DYN);

    void* pa = nullptr;
    cudaGetSymbolAddress(&pa, g_arrive);
    cudaMemsetAsync(pa, 0, sizeof(unsigned int));

    rnn_persistent<<<GRID, NTHREADS, SMEM_DYN>>>(x, h0, Wrec, Winp, tonic,
                                                 mask, sgn, out);
}